// round 1
// baseline (speedup 1.0000x reference)
#include <cuda_runtime.h>
#include <math.h>

#define NWIN 479
#define PP   33
#define IMG  256

// T'[i][a]: regrid+ifftshift-folded DFT matrix, complex, scale N per factor.
__device__ float2 g_T[PP * PP];

__global__ void build_T_kernel() {
    int idx = blockIdx.x * blockDim.x + threadIdx.x;
    if (idx >= PP * PP) return;
    int i = idx / PP;            // output row (post-ifftshift)
    int a = idx % PP;            // patch index 0..32 (signed a-16)
    int ii = (i + 16) % PP;      // undo ifftshift: out[i] = q_regrid[(i+16)%33]
    double c = (double)ii * (478.0 / 32.0);
    int n = (int)floor(c);
    if (n > NWIN - 2) n = NWIN - 2;          // clip to 477 (i=32 -> n=477, f=1)
    float f = (float)(c - (double)n);
    int as = a - 16;
    // theta_k = -2*as*(n+k)/479 in units of pi; reduce 2*as*(n+k) mod 958 exactly
    long long m1 = (long long)2 * as * (n + 1);
    long long m2 = (long long)2 * as * (n + 2);
    int r1 = (int)(m1 % 958); if (r1 < 0) r1 += 958;
    int r2 = (int)(m2 % 958); if (r2 < 0) r2 += 958;
    float t1 = -(float)r1 * (1.0f / 479.0f);
    float t2 = -(float)r2 * (1.0f / 479.0f);
    float s1, c1, s2, c2;
    sincospif(t1, &s1, &c1);
    sincospif(t2, &s2, &c2);
    float w0 = 1.0f - f, w1 = f;
    g_T[idx] = make_float2(479.0f * (w0 * c1 + w1 * c2),
                           479.0f * (w0 * s1 + w1 * s2));
}

__global__ __launch_bounds__(512, 2)
void taper_kernel(const float* __restrict__ ref,
                  const float* __restrict__ mov,
                  const int* __restrict__ xp,
                  const int* __restrict__ yp,
                  float* __restrict__ out, int B) {
    __shared__ float  patch[PP][PP + 1];
    __shared__ float2 Ts[PP][PP];
    __shared__ float2 U[PP][PP + 1];

    int b = blockIdx.x;
    const float* img;
    float* o;
    if (b < B) {
        img = ref + (size_t)b * IMG * IMG;
        o   = out + (size_t)b * PP * PP * 2;
    } else {
        img = mov + (size_t)(b - B) * IMG * IMG;
        o   = out + (size_t)B * PP * PP * 2 + (size_t)(b - B) * PP * PP * 2;
    }
    int x0 = xp ? *xp : 100;
    int y0 = yp ? *yp : 50;

    // Load 33x33 patch at (x0, y0) and the T matrix
    for (int idx = threadIdx.x; idx < PP * PP; idx += blockDim.x) {
        int r = idx / PP, cc = idx % PP;
        patch[r][cc] = img[(size_t)(x0 + r) * IMG + (y0 + cc)];
        Ts[r][cc] = g_T[idx];
    }
    __syncthreads();

    // Stage 1: U[a][j] = sum_b patch[a][b] * T[j][b]   (real x complex)
    for (int idx = threadIdx.x; idx < PP * PP; idx += blockDim.x) {
        int a = idx / PP, j = idx % PP;
        float re = 0.f, im = 0.f;
#pragma unroll
        for (int bb = 0; bb < PP; bb++) {
            float  p = patch[a][bb];
            float2 t = Ts[j][bb];
            re = fmaf(p, t.x, re);
            im = fmaf(p, t.y, im);
        }
        U[a][j] = make_float2(re, im);
    }
    __syncthreads();

    // Stage 2: out[i][j] = sum_a T[i][a] * U[a][j]     (complex x complex)
    for (int idx = threadIdx.x; idx < PP * PP; idx += blockDim.x) {
        int i = idx / PP, j = idx % PP;
        float re = 0.f, im = 0.f;
#pragma unroll
        for (int a = 0; a < PP; a++) {
            float2 t = Ts[i][a];
            float2 u = U[a][j];
            re = fmaf(t.x, u.x, re);
            re = fmaf(-t.y, u.y, re);
            im = fmaf(t.x, u.y, im);
            im = fmaf(t.y, u.x, im);
        }
        o[idx * 2]     = re;
        o[idx * 2 + 1] = im;
    }
}

extern "C" void kernel_launch(void* const* d_in, const int* in_sizes, int n_in,
                              void* d_out, int out_size) {
    const float* ref = (const float*)d_in[0];
    const float* mov = (const float*)d_in[1];
    const int* xp = (n_in > 2) ? (const int*)d_in[2] : nullptr;
    const int* yp = (n_in > 3) ? (const int*)d_in[3] : nullptr;
    float* out = (float*)d_out;
    int B = in_sizes[0] / (IMG * IMG);

    build_T_kernel<<<(PP * PP + 255) / 256, 256>>>();
    taper_kernel<<<2 * B, 512>>>(ref, mov, xp, yp, out, B);
}

// round 2
// speedup vs baseline: 1.1905x; 1.1905x over previous
#include <cuda_runtime.h>
#include <math.h>

#define PP   33
#define IMG  256
#define NT   1024

__global__ __launch_bounds__(NT, 1)
void taper_kernel(const float* __restrict__ ref,
                  const float* __restrict__ mov,
                  const int* __restrict__ xp,
                  const int* __restrict__ yp,
                  float* __restrict__ out, int B) {
    __shared__ float  patch[PP][PP + 1];
    __shared__ float2 Ts[PP][PP];      // Ts[i][a]  (row-major, for stage 2 broadcast)
    __shared__ float2 Tt[PP][PP];      // Tt[b][j] = Ts[j][b] (for stage 1 contiguous)
    __shared__ float2 U[PP][PP + 1];

    int b = blockIdx.x;
    const float* img;
    float2* o;
    if (b < B) {
        img = ref + (size_t)b * IMG * IMG;
        o   = (float2*)out + (size_t)b * PP * PP;
    } else {
        img = mov + (size_t)(b - B) * IMG * IMG;
        o   = (float2*)out + (size_t)B * PP * PP + (size_t)(b - B) * PP * PP;
    }
    int x0 = xp ? __ldg(xp) : 100;
    int y0 = yp ? __ldg(yp) : 50;

    int tid = threadIdx.x;

    // Load patch + compute T in-block (overlaps gmem latency with MUFU work)
    for (int idx = tid; idx < PP * PP; idx += NT) {
        int r = idx / PP, c = idx % PP;
        patch[r][c] = img[(size_t)(x0 + r) * IMG + (y0 + c)];

        // T'[r][c]: regrid + ifftshift folded DFT row r, patch offset c
        int ii  = (r + 16) % PP;             // undo ifftshift
        int n16 = 478 * ii;                  // c_reg = ii*478/32 exactly
        int n   = n16 >> 5;
        float f = (float)(n16 & 31) * (1.0f / 32.0f);
        int as  = c - 16;
        int m1 = (2 * as * (n + 1)) % 958; if (m1 < 0) m1 += 958;
        int m2 = (2 * as * (n + 2)) % 958; if (m2 < 0) m2 += 958;
        float s1, c1, s2, c2;
        sincospif(-(float)m1 * (1.0f / 479.0f), &s1, &c1);
        sincospif(-(float)m2 * (1.0f / 479.0f), &s2, &c2);
        float w0 = 479.0f * (1.0f - f), w1 = 479.0f * f;
        float2 t = make_float2(w0 * c1 + w1 * c2, w0 * s1 + w1 * s2);
        Ts[r][c] = t;
        Tt[c][r] = t;
    }
    __syncthreads();

    // Stage 1: U[a][j] = sum_b patch[a][b] * T[j][b]   (real x complex)
    for (int idx = tid; idx < PP * PP; idx += NT) {
        int a = idx / PP, j = idx % PP;
        float re = 0.f, im = 0.f;
#pragma unroll
        for (int bb = 0; bb < PP; bb++) {
            float  p = patch[a][bb];
            float2 t = Tt[bb][j];
            re = fmaf(p, t.x, re);
            im = fmaf(p, t.y, im);
        }
        U[a][j] = make_float2(re, im);
    }
    __syncthreads();

    // Stage 2: out[i][j] = sum_a T[i][a] * U[a][j]   (complex x complex)
    // Split re/im into independent accumulator pairs (halve the dep chain).
    for (int idx = tid; idx < PP * PP; idx += NT) {
        int i = idx / PP, j = idx % PP;
        float rxx = 0.f, ryy = 0.f, rxy = 0.f, ryx = 0.f;
#pragma unroll
        for (int a = 0; a < PP; a++) {
            float2 t = Ts[i][a];
            float2 u = U[a][j];
            rxx = fmaf(t.x, u.x, rxx);
            ryy = fmaf(t.y, u.y, ryy);
            rxy = fmaf(t.x, u.y, rxy);
            ryx = fmaf(t.y, u.x, ryx);
        }
        o[idx] = make_float2(rxx - ryy, rxy + ryx);
    }
}

extern "C" void kernel_launch(void* const* d_in, const int* in_sizes, int n_in,
                              void* d_out, int out_size) {
    const float* ref = (const float*)d_in[0];
    const float* mov = (const float*)d_in[1];
    const int* xp = (n_in > 2) ? (const int*)d_in[2] : nullptr;
    const int* yp = (n_in > 3) ? (const int*)d_in[3] : nullptr;
    float* out = (float*)d_out;
    int B = in_sizes[0] / (IMG * IMG);

    taper_kernel<<<2 * B, NT>>>(ref, mov, xp, yp, out, B);
}

// round 3
// speedup vs baseline: 1.1940x; 1.0030x over previous
#include <cuda_runtime.h>
#include <math.h>

#define PP   33
#define IMG  256
#define NT   1024

__global__ __launch_bounds__(NT, 1)
void taper_kernel(const float* __restrict__ ref,
                  const float* __restrict__ mov,
                  const int* __restrict__ xp,
                  const int* __restrict__ yp,
                  float* __restrict__ out, int B) {
    __shared__ float  patch[PP][PP + 3];   // row = 144B, 16B-aligned
    __shared__ float2 Ts[PP][PP + 1];      // Ts[i][a], row = 272B, 16B-aligned
    __shared__ float2 Tt[PP][PP + 1];      // Tt[b][j] = Ts[j][b]
    __shared__ float2 V[PP][PP + 1];       // V[i][b]

    int b = blockIdx.x;
    const float* img;
    float2* o;
    if (b < B) {
        img = ref + (size_t)b * IMG * IMG;
        o   = (float2*)out + (size_t)b * PP * PP;
    } else {
        img = mov + (size_t)(b - B) * IMG * IMG;
        o   = (float2*)out + (size_t)B * PP * PP + (size_t)(b - B) * PP * PP;
    }
    int x0 = xp ? __ldg(xp) : 100;
    int y0 = yp ? __ldg(yp) : 50;

    int tid = threadIdx.x;

    // Phase A: build T (no gmem dependence -> overlaps x0/patch load latency)
    // and stage the 33x33 patch.
    for (int idx = tid; idx < PP * PP; idx += NT) {
        int q = idx / PP;
        int r = idx - q * PP;

        // T'[q][r]: regrid + ifftshift folded DFT
        int ii  = q + 16; if (ii >= PP) ii -= PP;     // undo ifftshift
        int n16 = 478 * ii;                            // c_reg = ii*478/32 exact
        int n   = n16 >> 5;
        float f = (float)(n16 & 31) * 0.03125f;
        int as  = r - 16;
        float s1, c1, s2, c2;
        sincospif((float)(-2 * as * (n + 1)) * (1.0f / 479.0f), &s1, &c1);
        sincospif((float)(-2 * as * (n + 2)) * (1.0f / 479.0f), &s2, &c2);
        float w0 = 479.0f * (1.0f - f), w1 = 479.0f * f;
        float2 t = make_float2(fmaf(w0, c1, w1 * c2), fmaf(w0, s1, w1 * s2));
        Ts[q][r] = t;
        Tt[r][q] = t;

        patch[q][r] = img[(size_t)(x0 + q) * IMG + (y0 + r)];
    }
    __syncthreads();

    // Stage 1: V[i][b] = sum_a Ts[i][a] * patch[a][b]   (complex x real)
    // Ts row is a contiguous broadcast -> float4; patch column is lane-stride-1.
    for (int idx = tid; idx < PP * PP; idx += NT) {
        int i = idx / PP;
        int bb = idx - i * PP;
        const float4* trow = reinterpret_cast<const float4*>(Ts[i]);
        float rx = 0.f, ry = 0.f, rx2 = 0.f, ry2 = 0.f;
#pragma unroll
        for (int h = 0; h < 16; h++) {
            float4 tv = trow[h];                 // Ts[i][2h], Ts[i][2h+1]
            float p0 = patch[2 * h][bb];
            float p1 = patch[2 * h + 1][bb];
            rx  = fmaf(tv.x, p0, rx);
            ry  = fmaf(tv.y, p0, ry);
            rx2 = fmaf(tv.z, p1, rx2);
            ry2 = fmaf(tv.w, p1, ry2);
        }
        float2 tl = Ts[i][32];
        float  pl = patch[32][bb];
        V[i][bb] = make_float2(fmaf(tl.x, pl, rx + rx2),
                               fmaf(tl.y, pl, ry + ry2));
    }
    __syncthreads();

    // Stage 2: out[i][j] = sum_b V[i][b] * Tt[b][j]   (complex x complex)
    // V row is a contiguous broadcast -> float4; Tt row is lane-stride-1.
    for (int idx = tid; idx < PP * PP; idx += NT) {
        int i = idx / PP;
        int j = idx - i * PP;
        const float4* vrow = reinterpret_cast<const float4*>(V[i]);
        float rxx = 0.f, ryy = 0.f, rxy = 0.f, ryx = 0.f;
#pragma unroll
        for (int h = 0; h < 16; h++) {
            float4 vv = vrow[h];                 // V[i][2h], V[i][2h+1]
            float2 t0 = Tt[2 * h][j];
            float2 t1 = Tt[2 * h + 1][j];
            rxx = fmaf(vv.x, t0.x, rxx);
            ryy = fmaf(vv.y, t0.y, ryy);
            rxy = fmaf(vv.x, t0.y, rxy);
            ryx = fmaf(vv.y, t0.x, ryx);
            rxx = fmaf(vv.z, t1.x, rxx);
            ryy = fmaf(vv.w, t1.y, ryy);
            rxy = fmaf(vv.z, t1.y, rxy);
            ryx = fmaf(vv.w, t1.x, ryx);
        }
        float2 vl = V[i][32];
        float2 tl = Tt[32][j];
        rxx = fmaf(vl.x, tl.x, rxx);
        ryy = fmaf(vl.y, tl.y, ryy);
        rxy = fmaf(vl.x, tl.y, rxy);
        ryx = fmaf(vl.y, tl.x, ryx);
        o[idx] = make_float2(rxx - ryy, rxy + ryx);
    }
}

extern "C" void kernel_launch(void* const* d_in, const int* in_sizes, int n_in,
                              void* d_out, int out_size) {
    const float* ref = (const float*)d_in[0];
    const float* mov = (const float*)d_in[1];
    const int* xp = (n_in > 2) ? (const int*)d_in[2] : nullptr;
    const int* yp = (n_in > 3) ? (const int*)d_in[3] : nullptr;
    float* out = (float*)d_out;
    int B = in_sizes[0] / (IMG * IMG);

    taper_kernel<<<2 * B, NT>>>(ref, mov, xp, yp, out, B);
}